// round 14
// baseline (speedup 1.0000x reference)
#include <cuda_runtime.h>
#include <cuda_bf16.h>
#include <math.h>
#include <stdint.h>

// Problem constants
#define B_  16
#define N_  1024
#define IND 128
#define H_  4
#define D_  64
#define HD  256
#define NEG 0.2f

typedef unsigned long long ull;

// ---------------------------------------------------------------------------
// Scratch (allocation-free rule: __device__ globals)
// ---------------------------------------------------------------------------
__device__ float g_s[B_ * N_ * H_];
__device__ float g_t[B_ * N_ * H_];
__device__ float g_E[B_ * N_ * H_];
__device__ float g_F[B_ * N_ * H_];
__device__ float g_P[B_ * N_ * H_];
__device__ float g_Q[B_ * N_ * H_];
__device__ unsigned g_mask[32 * N_];                    // adjacency bits [jword][i]
// h^T split bf16: [b*H+head][d][j-pair packed 2xbf16/u32], 512 u32 per (bh,d) row
__device__ __align__(16) unsigned g_HT_hi[64 * 64 * 512];
__device__ __align__(16) unsigned g_HT_lo[64 * 64 * 512];

// split fp32 pair (w0=even, w1=odd) into bf16x2 hi-pack + bf16x2 residual pack
// (low half of the u32 = even element, matching mma fragment packing)
__device__ __forceinline__ void split2(float w0, float w1, uint32_t& hp, uint32_t& lp) {
    asm("cvt.rn.bf16x2.f32 %0, %1, %2;" : "=r"(hp) : "f"(w1), "f"(w0));
    float h0 = __uint_as_float(hp << 16);
    float h1 = __uint_as_float(hp & 0xffff0000u);
    asm("cvt.rn.bf16x2.f32 %0, %1, %2;" : "=r"(lp) : "f"(w1 - h1), "f"(w0 - h0));
}

// bf16 m16n8k16 HMMA, fp32 accumulate in place (sm_80+; no 'a'-gated features)
__device__ __forceinline__ void mma_bf16(float d[4], const uint32_t a[4],
                                         const uint32_t b[2]) {
    asm volatile(
        "mma.sync.aligned.m16n8k16.row.col.f32.bf16.bf16.f32 "
        "{%0,%1,%2,%3}, {%4,%5,%6,%7}, {%8,%9}, {%0,%1,%2,%3};"
        : "+f"(d[0]), "+f"(d[1]), "+f"(d[2]), "+f"(d[3])
        : "r"(a[0]), "r"(a[1]), "r"(a[2]), "r"(a[3]), "r"(b[0]), "r"(b[1]));
}

// ---------------------------------------------------------------------------
// Kernel 0: adjacency -> bitmask
// ---------------------------------------------------------------------------
__global__ __launch_bounds__(256) void gat_mask(const int* __restrict__ adj)
{
    __shared__ unsigned words[32];
    const int i   = blockIdx.x;
    const int tid = threadIdx.x;

    if (tid < 32) words[tid] = 0u;
    __syncthreads();

    int4 v = *(const int4*)&adj[i * N_ + tid * 4];
    unsigned nib = (v.x > 0 ? 1u : 0u) | (v.y > 0 ? 2u : 0u) |
                   (v.z > 0 ? 4u : 0u) | (v.w > 0 ? 8u : 0u);
    atomicOr(&words[tid >> 3], nib << ((tid & 7) * 4));
    __syncthreads();

    if (tid < 32) g_mask[tid * N_ + i] = words[tid];
}

// ---------------------------------------------------------------------------
// Kernel 1: h = x @ W; writes split-bf16 TRANSPOSED h (g_HT_hi/lo, d-major)
// plus s/t scores and their exp factors. grid (M/64, H), 256 threads.
// ---------------------------------------------------------------------------
__global__ __launch_bounds__(256) void gat_gemm1(
    const float* __restrict__ x, const float* __restrict__ W,
    const float* __restrict__ a_src, const float* __restrict__ a_dst)
{
    const int head = blockIdx.y;
    const int m0   = blockIdx.x * 64;
    const int tid  = threadIdx.x;
    const int tx   = tid & 15;
    const int ty   = tid >> 4;

    __shared__ float xsT[32][68];
    __shared__ float ws[32][68];
    __shared__ float asrc_s[64], adst_s[64];
    __shared__ float red[2][64][17];
    __shared__ unsigned Thi[64 * 33];   // transpose staging [d][n-pair]
    __shared__ unsigned Tlo[64 * 33];

    if (tid < 64) {
        asrc_s[tid] = a_src[head * 64 + tid];
        adst_s[tid] = a_dst[head * 64 + tid];
    }

    float acc[4][4];
#pragma unroll
    for (int i = 0; i < 4; i++)
#pragma unroll
        for (int j = 0; j < 4; j++) acc[i][j] = 0.f;

    for (int k0 = 0; k0 < IND; k0 += 32) {
#pragma unroll
        for (int it = 0; it < 2; ++it) {
            int idx = tid + it * 256;
            int r   = idx >> 3;
            int c4  = (idx & 7) * 4;
            float4 v = *(const float4*)&x[(m0 + r) * IND + k0 + c4];
            xsT[c4 + 0][r] = v.x;
            xsT[c4 + 1][r] = v.y;
            xsT[c4 + 2][r] = v.z;
            xsT[c4 + 3][r] = v.w;
        }
#pragma unroll
        for (int it = 0; it < 2; ++it) {
            int idx = tid + it * 256;
            int kk  = idx >> 4;
            int c4  = (idx & 15) * 4;
            *(float4*)&ws[kk][c4] =
                *(const float4*)&W[(k0 + kk) * HD + head * 64 + c4];
        }
        __syncthreads();

#pragma unroll
        for (int kk = 0; kk < 32; ++kk) {
            float4 a4 = *(const float4*)&xsT[kk][ty * 4];
            float4 b4 = *(const float4*)&ws[kk][tx * 4];
            float a[4] = {a4.x, a4.y, a4.z, a4.w};
            float b[4] = {b4.x, b4.y, b4.z, b4.w};
#pragma unroll
            for (int i = 0; i < 4; i++)
#pragma unroll
                for (int j = 0; j < 4; j++) acc[i][j] += a[i] * b[j];
        }
        __syncthreads();
    }

    // score partials + split-bf16 transpose pack
#pragma unroll
    for (int ri = 0; ri < 4; ri++) {
        int row = ty * 4 + ri;
        float sp = 0.f, tp = 0.f;
#pragma unroll
        for (int ci = 0; ci < 4; ci++) {
            int c = tx * 4 + ci;
            sp += acc[ri][ci] * asrc_s[c];
            tp += acc[ri][ci] * adst_s[c];
        }
        red[0][row][tx] = sp;
        red[1][row][tx] = tp;
    }
#pragma unroll
    for (int ci = 0; ci < 4; ci++) {
        int d = tx * 4 + ci;
#pragma unroll
        for (int q = 0; q < 2; q++) {
            uint32_t hp, lp;
            split2(acc[q * 2][ci], acc[q * 2 + 1][ci], hp, lp);
            Thi[d * 33 + ty * 2 + q] = hp;
            Tlo[d * 33 + ty * 2 + q] = lp;
        }
    }
    __syncthreads();

    // coalesced write-out of transposed tile
    {
        const int bq = m0 >> 10;
        const int n0 = m0 & 1023;
        const int bh = bq * H_ + head;
        int d = tid >> 2, q = tid & 3;
        unsigned* dh = &g_HT_hi[(unsigned)(bh * 64 + d) * 512 + (n0 >> 1) + q * 8];
        unsigned* dl = &g_HT_lo[(unsigned)(bh * 64 + d) * 512 + (n0 >> 1) + q * 8];
#pragma unroll
        for (int cc = 0; cc < 8; ++cc) {
            dh[cc] = Thi[d * 33 + q * 8 + cc];
            dl[cc] = Tlo[d * 33 + q * 8 + cc];
        }
    }

    if (tid < 64) {
        float s = 0.f, t = 0.f;
#pragma unroll
        for (int q = 0; q < 16; q++) { s += red[0][tid][q]; t += red[1][tid][q]; }
        int idx = (m0 + tid) * H_ + head;
        g_s[idx] = s;
        g_t[idx] = t;
        g_E[idx] = expf(s);
        g_F[idx] = expf(NEG * s);
        g_P[idx] = expf(t);
        g_Q[idx] = expf(NEG * t);
    }
}

// ---------------------------------------------------------------------------
// Kernel 2: fused masked-softmax aggregation on HMMA (mma.sync m16n8k16 bf16).
// grid (N/128, H, B), 128 threads = 4 warps; warp w owns i-rows iw..iw+31
// (2 m16 tiles) x all 64 d (8 n8 tiles). K = 1024 j in 16 chunks of 64.
// A fragments (attention weights) are synthesized IN-REGISTER per lane from
// the exp factorization + adjacency bits; B fragments load directly from
// g_HT (its [d][j-pair] u32 layout == the B fragment register format).
// Split-bf16 3-product per k-step for fp32-grade accuracy; Z exact in fp32.
// ---------------------------------------------------------------------------
__global__ __launch_bounds__(128, 3) void gat_attn(float* __restrict__ out)
{
    __shared__ float4 sJ[2][64];   // (t, P, Q, _) per j, double buffered

    const int b    = blockIdx.z;
    const int head = blockIdx.y;
    const int i0   = blockIdx.x * 128;
    const int tid  = threadIdx.x;
    const int w    = tid >> 5;
    const int l    = tid & 31;
    const int q    = l >> 2;           // fragment row group 0..7
    const int e2   = (l & 3) * 2;      // fragment col pair 0,2,4,6
    const int bh   = b * H_ + head;
    const int iw   = i0 + w * 32;

    // per-lane row constants for rows q, q+8, q+16, q+24 (within warp's 32)
    float si[4], Ei[4], Fi[4];
#pragma unroll
    for (int r = 0; r < 4; ++r) {
        int gi = (b * N_ + iw + q + 8 * r) * H_ + head;
        si[r] = g_s[gi]; Ei[r] = g_E[gi]; Fi[r] = g_F[gi];
    }
    float z[4] = {0.f, 0.f, 0.f, 0.f};

    unsigned rowbase[8];               // g_HT row offsets for this lane's d's
#pragma unroll
    for (int nt = 0; nt < 8; ++nt)
        rowbase[nt] = (unsigned)(bh * 64 + nt * 8 + q) * 512;

    float D[2][8][4];
#pragma unroll
    for (int mt = 0; mt < 2; ++mt)
#pragma unroll
        for (int nt = 0; nt < 8; ++nt)
#pragma unroll
            for (int k = 0; k < 4; ++k) D[mt][nt][k] = 0.f;

    for (int c = 0; c < 16; ++c) {
        const int j0 = c * 64;
        if (tid < 64) {
            int jg = (b * N_ + j0 + tid) * H_ + head;
            sJ[c & 1][tid] = make_float4(g_t[jg], g_P[jg], g_Q[jg], 0.f);
        }
        ull mrow[4];
#pragma unroll
        for (int r = 0; r < 4; ++r) {
            int ii = iw + q + 8 * r;
            mrow[r] = (ull)g_mask[(c * 2) * N_ + ii] |
                      ((ull)g_mask[(c * 2 + 1) * N_ + ii] << 32);
        }
        __syncthreads();               // sJ[c&1] visible (1 sync per chunk)
        const float4* sjb = sJ[c & 1];

#pragma unroll
        for (int ks = 0; ks < 4; ++ks) {
            // --- build A fragments for both m-tiles, hi + lo residual ---
            uint32_t ahi[2][4], alo[2][4];
#pragma unroll
            for (int kh = 0; kh < 2; ++kh) {
                int jl = ks * 16 + kh * 8 + e2;       // local j (0..63), even
                float4 f0 = sjb[jl], f1 = sjb[jl + 1];
#pragma unroll
                for (int r = 0; r < 4; ++r) {
                    float w0 = ((si[r] + f0.x) >= 0.f) ? Ei[r] * f0.y : Fi[r] * f0.z;
                    float w1 = ((si[r] + f1.x) >= 0.f) ? Ei[r] * f1.y : Fi[r] * f1.z;
                    w0 = ((mrow[r] >> jl) & 1ULL) ? w0 : 0.f;
                    w1 = ((mrow[r] >> (jl + 1)) & 1ULL) ? w1 : 0.f;
                    z[r] += w0 + w1;
                    uint32_t hp, lp;
                    split2(w0, w1, hp, lp);
                    int mt = r >> 1, ri = (r & 1) + kh * 2;
                    ahi[mt][ri] = hp;
                    alo[mt][ri] = lp;
                }
            }
            // --- B fragments straight from gmem; 3-product accumulate ---
            const unsigned wb = (unsigned)(j0 >> 1) + ks * 8 + (l & 3);
#pragma unroll
            for (int nt = 0; nt < 8; ++nt) {
                uint32_t bhi[2], blo[2];
                bhi[0] = g_HT_hi[rowbase[nt] + wb];
                bhi[1] = g_HT_hi[rowbase[nt] + wb + 4];
                blo[0] = g_HT_lo[rowbase[nt] + wb];
                blo[1] = g_HT_lo[rowbase[nt] + wb + 4];
#pragma unroll
                for (int mt = 0; mt < 2; ++mt) {
                    mma_bf16(D[mt][nt], ahi[mt], bhi);
                    mma_bf16(D[mt][nt], ahi[mt], blo);
                    mma_bf16(D[mt][nt], alo[mt], bhi);
                }
            }
        }
    }

    // Z: reduce over the 4 lanes of each quad (cols of the A fragment)
#pragma unroll
    for (int r = 0; r < 4; ++r) {
        z[r] += __shfl_xor_sync(0xffffffffu, z[r], 1);
        z[r] += __shfl_xor_sync(0xffffffffu, z[r], 2);
        z[r] = 1.f / z[r];
    }

    // store: D fragment lane map = rows (q+16mt, q+8+16mt), cols e2,e2+1 of nt
#pragma unroll
    for (int mt = 0; mt < 2; ++mt) {
        int r0 = iw + q + 16 * mt;
        float iz0 = z[2 * mt], iz1 = z[2 * mt + 1];
#pragma unroll
        for (int nt = 0; nt < 8; ++nt) {
            float2 v0 = make_float2(D[mt][nt][0] * iz0, D[mt][nt][1] * iz0);
            float2 v1 = make_float2(D[mt][nt][2] * iz1, D[mt][nt][3] * iz1);
            *(float2*)&out[(size_t)(b * N_ + r0) * HD + head * 64 + nt * 8 + e2] = v0;
            *(float2*)&out[(size_t)(b * N_ + r0 + 8) * HD + head * 64 + nt * 8 + e2] = v1;
        }
    }
}

extern "C" void kernel_launch(void* const* d_in, const int* in_sizes, int n_in,
                              void* d_out, int out_size)
{
    const float* x     = (const float*)d_in[0];
    const int*   adj   = (const int*)d_in[1];
    const float* W     = (const float*)d_in[2];
    const float* a_src = (const float*)d_in[3];
    const float* a_dst = (const float*)d_in[4];
    float*       out   = (float*)d_out;

    gat_mask<<<N_, 256>>>(adj);

    dim3 g1(B_ * N_ / 64, H_);
    gat_gemm1<<<g1, 256>>>(x, W, a_src, a_dst);

    dim3 g2(N_ / 128, H_, B_);
    gat_attn<<<g2, 128>>>(out);
}

// round 17
// speedup vs baseline: 2.4552x; 2.4552x over previous
#include <cuda_runtime.h>
#include <cuda_bf16.h>
#include <math.h>
#include <stdint.h>

// Problem constants
#define B_  16
#define N_  1024
#define IND 128
#define H_  4
#define D_  64
#define HD  256
#define NEG 0.2f

typedef unsigned long long ull;

// ---------------------------------------------------------------------------
// Scratch (allocation-free rule: __device__ globals)
// ---------------------------------------------------------------------------
__device__ float g_s[B_ * N_ * H_];
__device__ float g_t[B_ * N_ * H_];
__device__ float g_E[B_ * N_ * H_];
__device__ float g_F[B_ * N_ * H_];
__device__ float g_P[B_ * N_ * H_];
__device__ float g_Q[B_ * N_ * H_];
__device__ unsigned g_mask[32 * N_];                    // adjacency bits [jword][i]
// h^T split bf16: [b*H+head][d][j-pair packed 2xbf16/u32], 512 u32 per (bh,d) row
__device__ __align__(16) unsigned g_HT_hi[64 * 64 * 512];
__device__ __align__(16) unsigned g_HT_lo[64 * 64 * 512];

// split fp32 pair (w0=even, w1=odd) into bf16x2 hi-pack + bf16x2 residual pack
__device__ __forceinline__ void split2(float w0, float w1, uint32_t& hp, uint32_t& lp) {
    asm("cvt.rn.bf16x2.f32 %0, %1, %2;" : "=r"(hp) : "f"(w1), "f"(w0));
    float h0 = __uint_as_float(hp << 16);
    float h1 = __uint_as_float(hp & 0xffff0000u);
    asm("cvt.rn.bf16x2.f32 %0, %1, %2;" : "=r"(lp) : "f"(w1 - h1), "f"(w0 - h0));
}

// bf16 m16n8k16 HMMA, fp32 accumulate in place
__device__ __forceinline__ void mma_bf16(float d[4], const uint32_t a[4],
                                         uint32_t b0, uint32_t b1) {
    asm volatile(
        "mma.sync.aligned.m16n8k16.row.col.f32.bf16.bf16.f32 "
        "{%0,%1,%2,%3}, {%4,%5,%6,%7}, {%8,%9}, {%0,%1,%2,%3};"
        : "+f"(d[0]), "+f"(d[1]), "+f"(d[2]), "+f"(d[3])
        : "r"(a[0]), "r"(a[1]), "r"(a[2]), "r"(a[3]), "r"(b0), "r"(b1));
}

__device__ __forceinline__ uint32_t smem_u32(const void* p) {
    uint32_t a;
    asm("{ .reg .u64 t; cvta.to.shared.u64 t, %1; cvt.u32.u64 %0, t; }"
        : "=r"(a) : "l"(p));
    return a;
}

// ---------------------------------------------------------------------------
// Kernel 0: adjacency -> bitmask
// ---------------------------------------------------------------------------
__global__ __launch_bounds__(256) void gat_mask(const int* __restrict__ adj)
{
    __shared__ unsigned words[32];
    const int i   = blockIdx.x;
    const int tid = threadIdx.x;

    if (tid < 32) words[tid] = 0u;
    __syncthreads();

    int4 v = *(const int4*)&adj[i * N_ + tid * 4];
    unsigned nib = (v.x > 0 ? 1u : 0u) | (v.y > 0 ? 2u : 0u) |
                   (v.z > 0 ? 4u : 0u) | (v.w > 0 ? 8u : 0u);
    atomicOr(&words[tid >> 3], nib << ((tid & 7) * 4));
    __syncthreads();

    if (tid < 32) g_mask[tid * N_ + i] = words[tid];
}

// ---------------------------------------------------------------------------
// Kernel 1: h = x @ W; writes split-bf16 TRANSPOSED h (g_HT_hi/lo, d-major)
// plus s/t scores and exp factors. grid (M/64, H), 256 threads. (unchanged)
// ---------------------------------------------------------------------------
__global__ __launch_bounds__(256) void gat_gemm1(
    const float* __restrict__ x, const float* __restrict__ W,
    const float* __restrict__ a_src, const float* __restrict__ a_dst)
{
    const int head = blockIdx.y;
    const int m0   = blockIdx.x * 64;
    const int tid  = threadIdx.x;
    const int tx   = tid & 15;
    const int ty   = tid >> 4;

    __shared__ float xsT[32][68];
    __shared__ float ws[32][68];
    __shared__ float asrc_s[64], adst_s[64];
    __shared__ float red[2][64][17];
    __shared__ unsigned Thi[64 * 33];
    __shared__ unsigned Tlo[64 * 33];

    if (tid < 64) {
        asrc_s[tid] = a_src[head * 64 + tid];
        adst_s[tid] = a_dst[head * 64 + tid];
    }

    float acc[4][4];
#pragma unroll
    for (int i = 0; i < 4; i++)
#pragma unroll
        for (int j = 0; j < 4; j++) acc[i][j] = 0.f;

    for (int k0 = 0; k0 < IND; k0 += 32) {
#pragma unroll
        for (int it = 0; it < 2; ++it) {
            int idx = tid + it * 256;
            int r   = idx >> 3;
            int c4  = (idx & 7) * 4;
            float4 v = *(const float4*)&x[(m0 + r) * IND + k0 + c4];
            xsT[c4 + 0][r] = v.x;
            xsT[c4 + 1][r] = v.y;
            xsT[c4 + 2][r] = v.z;
            xsT[c4 + 3][r] = v.w;
        }
#pragma unroll
        for (int it = 0; it < 2; ++it) {
            int idx = tid + it * 256;
            int kk  = idx >> 4;
            int c4  = (idx & 15) * 4;
            *(float4*)&ws[kk][c4] =
                *(const float4*)&W[(k0 + kk) * HD + head * 64 + c4];
        }
        __syncthreads();

#pragma unroll
        for (int kk = 0; kk < 32; ++kk) {
            float4 a4 = *(const float4*)&xsT[kk][ty * 4];
            float4 b4 = *(const float4*)&ws[kk][tx * 4];
            float a[4] = {a4.x, a4.y, a4.z, a4.w};
            float b[4] = {b4.x, b4.y, b4.z, b4.w};
#pragma unroll
            for (int i = 0; i < 4; i++)
#pragma unroll
                for (int j = 0; j < 4; j++) acc[i][j] += a[i] * b[j];
        }
        __syncthreads();
    }

#pragma unroll
    for (int ri = 0; ri < 4; ri++) {
        int row = ty * 4 + ri;
        float sp = 0.f, tp = 0.f;
#pragma unroll
        for (int ci = 0; ci < 4; ci++) {
            int c = tx * 4 + ci;
            sp += acc[ri][ci] * asrc_s[c];
            tp += acc[ri][ci] * adst_s[c];
        }
        red[0][row][tx] = sp;
        red[1][row][tx] = tp;
    }
#pragma unroll
    for (int ci = 0; ci < 4; ci++) {
        int d = tx * 4 + ci;
#pragma unroll
        for (int q = 0; q < 2; q++) {
            uint32_t hp, lp;
            split2(acc[q * 2][ci], acc[q * 2 + 1][ci], hp, lp);
            Thi[d * 33 + ty * 2 + q] = hp;
            Tlo[d * 33 + ty * 2 + q] = lp;
        }
    }
    __syncthreads();

    {
        const int bq = m0 >> 10;
        const int n0 = m0 & 1023;
        const int bh = bq * H_ + head;
        int d = tid >> 2, q = tid & 3;
        unsigned* dh = &g_HT_hi[(unsigned)(bh * 64 + d) * 512 + (n0 >> 1) + q * 8];
        unsigned* dl = &g_HT_lo[(unsigned)(bh * 64 + d) * 512 + (n0 >> 1) + q * 8];
#pragma unroll
        for (int cc = 0; cc < 8; ++cc) {
            dh[cc] = Thi[d * 33 + q * 8 + cc];
            dl[cc] = Tlo[d * 33 + q * 8 + cc];
        }
    }

    if (tid < 64) {
        float s = 0.f, t = 0.f;
#pragma unroll
        for (int q = 0; q < 16; q++) { s += red[0][tid][q]; t += red[1][tid][q]; }
        int idx = (m0 + tid) * H_ + head;
        g_s[idx] = s;
        g_t[idx] = t;
        g_E[idx] = expf(s);
        g_F[idx] = expf(NEG * s);
        g_P[idx] = expf(t);
        g_Q[idx] = expf(NEG * t);
    }
}

// ---------------------------------------------------------------------------
// Kernel 2: fused masked-softmax aggregation on HMMA.
// grid (N/128, H, B), 256 threads = 8 warps; warp w owns 16 i-rows (one m16
// tile) x 64 d. B tiles (h^T hi/lo) staged in SMEM once per 64-j chunk,
// shared by all warps, read via ldmatrix.m8n8.x4 (conflict-free via 144B row
// pad). A fragments synthesized in-register from exp factorization + bits.
// Split-bf16 3-product accumulate; Z exact fp32 + quad shuffle reduce.
// ---------------------------------------------------------------------------
#define PADW 36   // B-tile row stride in u32 (144 bytes): conflict-free ldmatrix

__global__ __launch_bounds__(256, 2) void gat_attn(float* __restrict__ out)
{
    __shared__ unsigned sBhi[64 * PADW];
    __shared__ unsigned sBlo[64 * PADW];
    __shared__ float4 sJ[64];

    const int b    = blockIdx.z;
    const int head = blockIdx.y;
    const int i0   = blockIdx.x * 128;
    const int tid  = threadIdx.x;
    const int w    = tid >> 5;
    const int l    = tid & 31;
    const int q    = l >> 2;           // fragment row group 0..7
    const int e2   = (l & 3) * 2;      // fragment col pair 0,2,4,6
    const int bh   = b * H_ + head;
    const int iw   = i0 + w * 16;      // this warp's 16 i-rows

    // row constants for rows q, q+8
    float si[2], Ei[2], Fi[2];
#pragma unroll
    for (int r = 0; r < 2; ++r) {
        int gi = (b * N_ + iw + q + 8 * r) * H_ + head;
        si[r] = g_s[gi]; Ei[r] = g_E[gi]; Fi[r] = g_F[gi];
    }
    float z[2] = {0.f, 0.f};

    float D[8][4];
#pragma unroll
    for (int nt = 0; nt < 8; ++nt)
#pragma unroll
        for (int k = 0; k < 4; ++k) D[nt][k] = 0.f;

    // staging identity: thread covers (d, 16B-chunk) pairs
    const int sd0 = tid >> 3, sc0 = tid & 7;           // idx = tid
    const int sd1 = (tid + 256) >> 3, sc1 = tid & 7;   // idx = tid + 256
    const uint4* GH = (const uint4*)g_HT_hi;
    const uint4* GL = (const uint4*)g_HT_lo;

    // ldmatrix lane address (byte offset into B tile), ks advances +32B
    const int lm_d  = ((l >> 4) << 3) + (l & 7);   // within 16-d pair group
    const int lm_kh = (l >> 3) & 1;
    const uint32_t bhiBase = smem_u32(sBhi);
    const uint32_t bloBase = smem_u32(sBlo);

    // prefetch chunk 0
    uint4 ph0, ph1, pl0, pl1;
    float pt = 0.f, pp = 0.f, pq = 0.f;
    {
        ph0 = GH[(unsigned)(bh * 64 + sd0) * 128 + sc0];
        ph1 = GH[(unsigned)(bh * 64 + sd1) * 128 + sc1];
        pl0 = GL[(unsigned)(bh * 64 + sd0) * 128 + sc0];
        pl1 = GL[(unsigned)(bh * 64 + sd1) * 128 + sc1];
        if (tid < 64) {
            int jg = (b * N_ + tid) * H_ + head;
            pt = g_t[jg]; pp = g_P[jg]; pq = g_Q[jg];
        }
    }

    for (int c = 0; c < 16; ++c) {
        __syncthreads();   // previous chunk's smem reads complete
        *(uint4*)&sBhi[sd0 * PADW + sc0 * 4] = ph0;
        *(uint4*)&sBhi[sd1 * PADW + sc1 * 4] = ph1;
        *(uint4*)&sBlo[sd0 * PADW + sc0 * 4] = pl0;
        *(uint4*)&sBlo[sd1 * PADW + sc1 * 4] = pl1;
        if (tid < 64) sJ[tid] = make_float4(pt, pp, pq, 0.f);

        if (c < 15) {      // prefetch next chunk (latency hidden by compute)
            int nc = c + 1;
            ph0 = GH[(unsigned)(bh * 64 + sd0) * 128 + nc * 8 + sc0];
            ph1 = GH[(unsigned)(bh * 64 + sd1) * 128 + nc * 8 + sc1];
            pl0 = GL[(unsigned)(bh * 64 + sd0) * 128 + nc * 8 + sc0];
            pl1 = GL[(unsigned)(bh * 64 + sd1) * 128 + nc * 8 + sc1];
            if (tid < 64) {
                int jg = (b * N_ + nc * 64 + tid) * H_ + head;
                pt = g_t[jg]; pp = g_P[jg]; pq = g_Q[jg];
            }
        }
        ull mrow[2];
#pragma unroll
        for (int r = 0; r < 2; ++r) {
            int ii = iw + q + 8 * r;
            mrow[r] = (ull)g_mask[(c * 2) * N_ + ii] |
                      ((ull)g_mask[(c * 2 + 1) * N_ + ii] << 32);
        }
        __syncthreads();   // staged tiles visible

#pragma unroll
        for (int ks = 0; ks < 4; ++ks) {
            // --- A fragments (16 rows x k16), hi + lo residual ---
            uint32_t ahi[4], alo[4];
#pragma unroll
            for (int kh = 0; kh < 2; ++kh) {
                int jl = ks * 16 + kh * 8 + e2;
                float4 f0 = sJ[jl], f1 = sJ[jl + 1];
#pragma unroll
                for (int r = 0; r < 2; ++r) {
                    float w0 = ((si[r] + f0.x) >= 0.f) ? Ei[r] * f0.y : Fi[r] * f0.z;
                    float w1 = ((si[r] + f1.x) >= 0.f) ? Ei[r] * f1.y : Fi[r] * f1.z;
                    w0 = ((mrow[r] >> jl) & 1ULL) ? w0 : 0.f;
                    w1 = ((mrow[r] >> (jl + 1)) & 1ULL) ? w1 : 0.f;
                    z[r] += w0 + w1;
                    split2(w0, w1, ahi[r + kh * 2], alo[r + kh * 2]);
                }
            }
            // --- B fragments via ldmatrix.x4 (2 n-tiles each), 3-product ---
            const uint32_t koff = (uint32_t)(ks * 32 + lm_kh * 16);
#pragma unroll
            for (int ntp = 0; ntp < 4; ++ntp) {
                uint32_t aoff = (uint32_t)(ntp * 16 + lm_d) * (PADW * 4) + koff;
                uint32_t h0, h1, h2, h3, l0, l1, l2, l3;
                asm volatile(
                    "ldmatrix.sync.aligned.m8n8.x4.shared.b16 {%0,%1,%2,%3}, [%4];"
                    : "=r"(h0), "=r"(h1), "=r"(h2), "=r"(h3) : "r"(bhiBase + aoff));
                asm volatile(
                    "ldmatrix.sync.aligned.m8n8.x4.shared.b16 {%0,%1,%2,%3}, [%4];"
                    : "=r"(l0), "=r"(l1), "=r"(l2), "=r"(l3) : "r"(bloBase + aoff));
                mma_bf16(D[ntp * 2],     ahi, h0, h1);
                mma_bf16(D[ntp * 2],     ahi, l0, l1);
                mma_bf16(D[ntp * 2],     alo, h0, h1);
                mma_bf16(D[ntp * 2 + 1], ahi, h2, h3);
                mma_bf16(D[ntp * 2 + 1], ahi, l2, l3);
                mma_bf16(D[ntp * 2 + 1], alo, h2, h3);
            }
        }
    }

    // Z: reduce across the quad (A-fragment columns live in lanes l&3)
#pragma unroll
    for (int r = 0; r < 2; ++r) {
        z[r] += __shfl_xor_sync(0xffffffffu, z[r], 1);
        z[r] += __shfl_xor_sync(0xffffffffu, z[r], 2);
        z[r] = 1.f / z[r];
    }

    // store: D lane map = rows (q, q+8), cols e2,e2+1 of each n-tile
#pragma unroll
    for (int nt = 0; nt < 8; ++nt) {
        float2 v0 = make_float2(D[nt][0] * z[0], D[nt][1] * z[0]);
        float2 v1 = make_float2(D[nt][2] * z[1], D[nt][3] * z[1]);
        *(float2*)&out[(size_t)(b * N_ + iw + q) * HD + head * 64 + nt * 8 + e2] = v0;
        *(float2*)&out[(size_t)(b * N_ + iw + q + 8) * HD + head * 64 + nt * 8 + e2] = v1;
    }
}

extern "C" void kernel_launch(void* const* d_in, const int* in_sizes, int n_in,
                              void* d_out, int out_size)
{
    const float* x     = (const float*)d_in[0];
    const int*   adj   = (const int*)d_in[1];
    const float* W     = (const float*)d_in[2];
    const float* a_src = (const float*)d_in[3];
    const float* a_dst = (const float*)d_in[4];
    float*       out   = (float*)d_out;

    gat_mask<<<N_, 256>>>(adj);

    dim3 g1(B_ * N_ / 64, H_);
    gat_gemm1<<<g1, 256>>>(x, W, a_src, a_dst);

    dim3 g2(N_ / 128, H_, B_);
    gat_attn<<<g2, 256>>>(out);
}